// round 12
// baseline (speedup 1.0000x reference)
#include <cuda_runtime.h>
#include <cuda_fp16.h>
#include <cstdint>

// VQ: B=16, N=4096, D=128, M=2048
// out layout (float32): quantized_st[8388608], loss[1], perp[1], indices[65536]

#define BN_TOTAL 65536
#define M_CB     2048
#define D_DIM    128
#define Q_ELEMS  8388608
#define LOSS_OFF 8388608
#define PERP_OFF 8388609
#define IDX_OFF  8388610

#define ROW_PITCH   272u                 // 136 fp16 per row (128 data + 8 pad)
#define SPLIT_BYTES (M_CB * ROW_PITCH)   // 557056 per split image
#define A_SPLIT     17408u               // 64 rows * 272 (per split)
#define B_SPLIT     17408u               // 64 rows * 272
#define B_BUF       34816u               // 2 splits (hi, mid)
#define NUM_NT      32

#define THRESH      2.0e-3f              // ~7x the rigorous approx-dist error bound
#define U64MAX      0xFFFFFFFFFFFFFFFFull

// SMEM map (bytes). A staging image OVERLAYS B buf0 (same 34816 size):
// A is consumed into registers before the first B load lands.
#define SM_AB     0u                     // 2 B bufs * 34816 = 69632 (buf0 = A image first)
#define SM_L2K    69632u                 // 8192
#define SM_L2Q    77824u                 // 256
#define SM_CAND   78080u                 // 64 rows * 4 u64 = 2048
#define SM_BEST   80128u                 // 256
#define SM_WSUM   80384u                 // 32
#define SM_TOTAL  80416u

__device__ float g_l2k[M_CB];
__device__ int   g_counts[M_CB];
__device__ float g_loss;
__device__ __align__(256) unsigned char g_wsplit[2u * SPLIT_BYTES];

// ---------------------------------------------------------------------------
__device__ __forceinline__ uint32_t smem_to_u32(const void* p) {
    uint32_t a;
    asm("{ .reg .u64 t; cvta.to.shared.u64 t, %1; cvt.u32.u64 %0, t; }"
        : "=r"(a) : "l"(p));
    return a;
}
__device__ __forceinline__ void cp16(uint32_t dst, const void* src) {
    asm volatile("cp.async.cg.shared.global [%0], [%1], 16;"
                 :: "r"(dst), "l"(src) : "memory");
}
__device__ __forceinline__ void cp_commit() {
    asm volatile("cp.async.commit_group;" ::: "memory");
}
__device__ __forceinline__ void cp_wait0() {
    asm volatile("cp.async.wait_group 0;" ::: "memory");
}
__device__ __forceinline__ void ldsm4(uint32_t* r, uint32_t addr) {
    asm volatile("ldmatrix.sync.aligned.m8n8.x4.shared.b16 {%0,%1,%2,%3}, [%4];"
                 : "=r"(r[0]), "=r"(r[1]), "=r"(r[2]), "=r"(r[3]) : "r"(addr));
}
__device__ __forceinline__ void mma_f16(float* d, const uint32_t* a, const uint32_t* b) {
    asm volatile(
        "mma.sync.aligned.m16n8k16.row.col.f32.f16.f16.f32 "
        "{%0,%1,%2,%3}, {%4,%5,%6,%7}, {%8,%9}, {%0,%1,%2,%3};"
        : "+f"(d[0]), "+f"(d[1]), "+f"(d[2]), "+f"(d[3])
        : "r"(a[0]), "r"(a[1]), "r"(a[2]), "r"(a[3]), "r"(b[0]), "r"(b[1]));
}
__device__ __forceinline__ void split2h(float v, __half& h, __half& m) {
    h = __float2half_rn(v);
    float r1 = __fsub_rn(v, __half2float(h));
    m = __float2half_rn(r1);
}
// branchless packed top-2: p = (float_bits << 32) | index.
// dists are all >> 0 so unsigned u64 order == (value, index) lexicographic.
__device__ __forceinline__ void t2upd(unsigned long long& b1, unsigned long long& b2,
                                      float v, unsigned n) {
    unsigned long long p =
        ((unsigned long long)__float_as_uint(v) << 32) | (unsigned long long)n;
    unsigned long long mx = p > b1 ? p : b1;
    b1 = p < b1 ? p : b1;
    b2 = mx < b2 ? mx : b2;
}
__device__ __forceinline__ unsigned long long shfl_xor_u64(unsigned long long v, int off) {
    uint32_t lo = (uint32_t)v, hi = (uint32_t)(v >> 32);
    lo = __shfl_xor_sync(0xffffffffu, lo, off);
    hi = __shfl_xor_sync(0xffffffffu, hi, off);
    return ((unsigned long long)hi << 32) | lo;
}

// ---------------------------------------------------------------------------
__global__ void noop_kernel() {}

// ---------------------------------------------------------------------------
// prep: codebook hi/mid fp16 splits into padded gmem images + ||k||^2 + zeroing
// ---------------------------------------------------------------------------
__global__ void prep_kernel(const float* __restrict__ w) {
    const int oct = blockIdx.x * 256 + threadIdx.x;   // 0..32767
    {
        int n = oct >> 4, k0 = (oct & 15) << 3;
        const float* src = w + (size_t)n * D_DIM + k0;
        __align__(16) __half hi[8], mi[8];
#pragma unroll
        for (int j = 0; j < 8; j++) split2h(src[j], hi[j], mi[j]);
        uint32_t off = (uint32_t)n * ROW_PITCH + (uint32_t)k0 * 2;
        *(uint4*)(g_wsplit + off)               = *(uint4*)hi;
        *(uint4*)(g_wsplit + SPLIT_BYTES + off) = *(uint4*)mi;
    }
    if (oct < M_CB) {
        const float* wr = w + (size_t)oct * D_DIM;
        float s = 0.f;
        for (int i = 0; i < D_DIM; i++)
            s = __fadd_rn(s, __fmul_rn(wr[i], wr[i]));   // strict sequential
        g_l2k[oct]    = s;
        g_counts[oct] = 0;
        if (oct == 0) g_loss = 0.f;
    }
}

// ---------------------------------------------------------------------------
__device__ __forceinline__ void load_b(uint32_t sb, int buf, int nt, int tid) {
#pragma unroll
    for (int s = 0; s < 2; s++) {
        const unsigned char* src =
            g_wsplit + (size_t)s * SPLIT_BYTES + (size_t)nt * B_SPLIT;
        uint32_t dst = sb + SM_AB + (uint32_t)buf * B_BUF + (uint32_t)s * B_SPLIT;
        for (int i = tid; i < (int)(B_SPLIT / 16); i += 256)
            cp16(dst + (uint32_t)i * 16u, src + (size_t)i * 16);
    }
}

__device__ __forceinline__ float exact_dist(const float* __restrict__ xrow,
                                            const float* __restrict__ w,
                                            int n, float l2q, float l2k) {
    const float4* wr = (const float4*)(w + (size_t)n * D_DIM);
    const float4* xr = (const float4*)xrow;
    float ps = 0.f;
#pragma unroll
    for (int i = 0; i < 32; i++) {
        float4 a = xr[i], b = wr[i];
        ps = __fmaf_rn(a.x, b.x, ps);
        ps = __fmaf_rn(a.y, b.y, ps);
        ps = __fmaf_rn(a.z, b.z, ps);
        ps = __fmaf_rn(a.w, b.w, ps);
    }
    return __fmaf_rn(-2.f, ps, __fadd_rn(l2q, l2k));
}

// ---------------------------------------------------------------------------
// main: M=64 query tile per CTA, 256 threads (8 warps, 4(M) x 2(N)),
// 2 CTAs/SM. A fragments register-resident; 3-pass fp16-split HMMA sweep
// with EVEN/ODD-chunk accumulator split (8 independent MMA chains/warp
// instead of 4 -> hides HMMA latency); packed top-2; exact fp32 refine.
// ---------------------------------------------------------------------------
__global__ __launch_bounds__(256, 2)
void vq_main_kernel(const float* __restrict__ x, const float* __restrict__ w,
                    float* __restrict__ out)
{
    extern __shared__ char smem[];
    const uint32_t sb = smem_to_u32(smem);
    const int tid = threadIdx.x;
    const int wid = tid >> 5, l = tid & 31;
    const int wx = wid & 3, wy = wid >> 2;        // wx: M (4 x 16 rows), wy: N (2 x 32 cols)
    const int lq = l >> 2, lr = l & 3;
    const int m0 = blockIdx.x * 64;

    float* l2k_s  = (float*)(smem + SM_L2K);
    float* l2q_s  = (float*)(smem + SM_L2Q);
    unsigned long long* cand = (unsigned long long*)(smem + SM_CAND);  // [64][4]
    int*   best_s = (int*)  (smem + SM_BEST);
    float* wsum   = (float*)(smem + SM_WSUM);

    // ---- build A split images (hi/mid fp16) in B-buf0 region (overlay)
#pragma unroll
    for (int i = 0; i < 4; i++) {
        int idx = tid + (i << 8);               // 0..1023 octets (64 rows x 16)
        int r = idx >> 4, k0 = (idx & 15) << 3;
        const float4* src = (const float4*)(x + (size_t)(m0 + r) * D_DIM + k0);
        float4 v0 = src[0], v1 = src[1];
        float vv[8] = {v0.x, v0.y, v0.z, v0.w, v1.x, v1.y, v1.z, v1.w};
        __align__(16) __half hi[8], mi[8];
#pragma unroll
        for (int j = 0; j < 8; j++) split2h(vv[j], hi[j], mi[j]);
        uint32_t off = SM_AB + (uint32_t)r * ROW_PITCH + (uint32_t)k0 * 2;
        *(uint4*)(smem + off)           = *(uint4*)hi;
        *(uint4*)(smem + off + A_SPLIT) = *(uint4*)mi;
    }
    // ---- stage l2k (512 float4 = 2048 floats)
    ((float4*)l2k_s)[tid]       = ((const float4*)g_l2k)[tid];
    ((float4*)l2k_s)[tid + 256] = ((const float4*)g_l2k)[tid + 256];
    // ---- l2q per row: strict sequential fp32 (reference rounding)
    if (tid < 64) {
        const float* xr = x + (size_t)(m0 + tid) * D_DIM;
        float s = 0.f;
        for (int k = 0; k < D_DIM; k++)
            s = __fadd_rn(s, __fmul_rn(xr[k], xr[k]));
        l2q_s[tid] = s;
    }
    __syncthreads();     // A image visible

    // ---- load A fragments ONCE (register-resident: 2 splits x 8 chunks x 4)
    uint32_t aF[2][8][4];
    {
        uint32_t row = (uint32_t)(wx * 16) + (uint32_t)(l & 15);
        uint32_t kbl = (uint32_t)((l >> 4) & 1) * 16u;
        uint32_t base = sb + SM_AB + row * ROW_PITCH + kbl;
#pragma unroll
        for (int s = 0; s < 2; s++)
#pragma unroll
            for (int c = 0; c < 8; c++)
                ldsm4(aF[s][c], base + (uint32_t)s * A_SPLIT + (uint32_t)c * 32u);
    }
    float lqr[2];
    lqr[0] = l2q_s[wx * 16 + lq];
    lqr[1] = l2q_s[wx * 16 + lq + 8];
    __syncthreads();     // A image consumed -> buf0 free for B

    // first B tile into buf0 (overwrites A image)
    load_b(sb, 0, 0, tid);
    cp_commit();

    // B lane base; buf offset added per tile
    uint32_t bBase;
    {
        uint32_t row = (uint32_t)(wy * 32) + (uint32_t)(l & 7) + (uint32_t)((l >> 4) & 1) * 8u;
        uint32_t kbl = (uint32_t)((l >> 3) & 1) * 16u;
        bBase = sb + SM_AB + row * ROW_PITCH + kbl;
    }

    unsigned long long t1[2] = {U64MAX, U64MAX};
    unsigned long long t2[2] = {U64MAX, U64MAX};

    for (int nt = 0; nt < NUM_NT; nt++) {
        cp_wait0();          // tile nt arrived (only group in flight)
        __syncthreads();     // visible to all; all warps done with other buf
        if (nt + 1 < NUM_NT) {
            load_b(sb, (nt + 1) & 1, nt + 1, tid);
            cp_commit();
        }

        // even/odd-chunk accumulator split: 8 independent chains per warp
        float acc[2][4][4];
#pragma unroll
        for (int e = 0; e < 2; e++)
#pragma unroll
            for (int n8 = 0; n8 < 4; n8++)
#pragma unroll
                for (int q = 0; q < 4; q++) acc[e][n8][q] = 0.f;

        const uint32_t bOff = (uint32_t)(nt & 1) * B_BUF;

#pragma unroll
        for (int c = 0; c < 8; c++) {
            const uint32_t kb = (uint32_t)c * 32u;
            const int e = c & 1;
            uint32_t bF[2][2][4];    // [split][ni16][reg]
#pragma unroll
            for (int s = 0; s < 2; s++)
#pragma unroll
                for (int g = 0; g < 2; g++)
                    ldsm4(bF[s][g],
                          bBase + bOff + (uint32_t)s * B_SPLIT
                                + (uint32_t)g * (16u * ROW_PITCH) + kb);

            // passes: hh, hM, mH
            const int PA[3] = {0, 0, 1};
            const int PB[3] = {0, 1, 0};
#pragma unroll
            for (int p = 0; p < 3; p++)
#pragma unroll
                for (int n8 = 0; n8 < 4; n8++)
                    mma_f16(acc[e][n8], aF[PA[p]][c], &bF[PB[p]][n8 >> 1][(n8 & 1) * 2]);
        }

        // epilogue: merge even/odd accs, packed top-2 (ascending index order)
#pragma unroll
        for (int n8 = 0; n8 < 4; n8++) {
            const int col0 = nt * 64 + wy * 32 + n8 * 8 + (lr << 1);
            const float2 lk = *(const float2*)(l2k_s + col0);
            float v;
            v = __fmaf_rn(-2.f, __fadd_rn(acc[0][n8][0], acc[1][n8][0]),
                          __fadd_rn(lqr[0], lk.x));
            t2upd(t1[0], t2[0], v, (unsigned)col0);
            v = __fmaf_rn(-2.f, __fadd_rn(acc[0][n8][1], acc[1][n8][1]),
                          __fadd_rn(lqr[0], lk.y));
            t2upd(t1[0], t2[0], v, (unsigned)(col0 + 1));
            v = __fmaf_rn(-2.f, __fadd_rn(acc[0][n8][2], acc[1][n8][2]),
                          __fadd_rn(lqr[1], lk.x));
            t2upd(t1[1], t2[1], v, (unsigned)col0);
            v = __fmaf_rn(-2.f, __fadd_rn(acc[0][n8][3], acc[1][n8][3]),
                          __fadd_rn(lqr[1], lk.y));
            t2upd(t1[1], t2[1], v, (unsigned)(col0 + 1));
        }
        // no trailing barrier: next iteration's barrier protects buffer reuse
    }

    // ---- merge top-2 across the 4 lanes (lr) sharing each row
#pragma unroll
    for (int h = 0; h < 2; h++) {
        unsigned long long b1 = t1[h], b2 = t2[h];
#pragma unroll
        for (int off = 1; off <= 2; off <<= 1) {
            unsigned long long o1 = shfl_xor_u64(b1, off);
            unsigned long long o2 = shfl_xor_u64(b2, off);
            unsigned long long mx = b1 > o1 ? b1 : o1;
            b1 = b1 < o1 ? b1 : o1;
            unsigned long long mn2 = b2 < o2 ? b2 : o2;
            b2 = mn2 < mx ? mn2 : mx;
        }
        if (lr == 0) {
            int row = wx * 16 + h * 8 + lq;
            cand[row * 4 + wy * 2 + 0] = b1;
            cand[row * 4 + wy * 2 + 1] = b2;
        }
    }
    __syncthreads();

    // ---- per-row final scan + rare exact refine
    if (tid < 64) {
        unsigned long long b1 = U64MAX, b2 = U64MAX;
#pragma unroll
        for (int j = 0; j < 4; j++) {
            unsigned long long p = cand[tid * 4 + j];
            unsigned long long mx = p > b1 ? p : b1;
            b1 = p < b1 ? p : b1;
            b2 = mx < b2 ? mx : b2;
        }
        float v1 = __uint_as_float((uint32_t)(b1 >> 32));
        float v2 = __uint_as_float((uint32_t)(b2 >> 32));
        int best = (int)(uint32_t)(b1 & 0xFFFFFFFFu);
        if (v2 - v1 <= THRESH) {
            const float* xrow = x + (size_t)(m0 + tid) * D_DIM;
            const float l2q_r = l2q_s[tid];
            float bd = 3.0e38f;
            int   bi = 0x7fffffff;
#pragma unroll
            for (int j = 0; j < 4; j++) {
                unsigned long long p = cand[tid * 4 + j];
                float pv = __uint_as_float((uint32_t)(p >> 32));
                if (pv <= v1 + THRESH) {
                    int n = (int)(uint32_t)(p & 0xFFFFFFFFu);
                    float d = exact_dist(xrow, w, n, l2q_r, l2k_s[n]);
                    if (d < bd || (d == bd && n < bi)) { bd = d; bi = n; }
                }
            }
            best = bi;
        }
        best_s[tid] = best;
        atomicAdd(&g_counts[best], 1);
        out[IDX_OFF + m0 + tid] = (float)best;
    }
    __syncthreads();

    // ---- gather z, quantized_st = x + (z - x), loss partial (quarter-row/thread)
    {
        const int r  = tid >> 2;
        const int kb = (tid & 3) << 5;
        const int best = best_s[r];
        const float4* xr = (const float4*)(x + (size_t)(m0 + r) * D_DIM + kb);
        const float4* wz = (const float4*)(w + (size_t)best * D_DIM + kb);
        float4* oq = (float4*)(out + (size_t)(m0 + r) * D_DIM + kb);
        float lsum = 0.f;
#pragma unroll
        for (int i = 0; i < 8; i++) {
            float4 xv = xr[i], z = wz[i];
            float4 qv;
            qv.x = __fadd_rn(xv.x, __fsub_rn(z.x, xv.x));
            qv.y = __fadd_rn(xv.y, __fsub_rn(z.y, xv.y));
            qv.z = __fadd_rn(xv.z, __fsub_rn(z.z, xv.z));
            qv.w = __fadd_rn(xv.w, __fsub_rn(z.w, xv.w));
            oq[i] = qv;
            float d0 = __fsub_rn(qv.x, xv.x), d1 = __fsub_rn(qv.y, xv.y);
            float d2 = __fsub_rn(qv.z, xv.z), d3 = __fsub_rn(qv.w, xv.w);
            lsum += d0 * d0 + d1 * d1 + d2 * d2 + d3 * d3;
        }
#pragma unroll
        for (int o = 16; o > 0; o >>= 1)
            lsum += __shfl_down_sync(0xffffffffu, lsum, o);
        if ((tid & 31) == 0) wsum[wid] = lsum;
    }
    __syncthreads();
    if (tid == 0) {
        float s = 0.f;
#pragma unroll
        for (int i = 0; i < 8; i++) s += wsum[i];
        atomicAdd(&g_loss, s);
    }
}

// ---------------------------------------------------------------------------
// finalize: loss mean + perplexity
// ---------------------------------------------------------------------------
__global__ void finalize_kernel(float* __restrict__ out) {
    int t = threadIdx.x;
    float s = 0.f;
    for (int i = t; i < M_CB; i += 256) {
        float p = (float)g_counts[i] * (1.0f / 65536.0f);
        s += p * logf(p + 1e-10f);
    }
#pragma unroll
    for (int o = 16; o > 0; o >>= 1)
        s += __shfl_down_sync(0xffffffffu, s, o);
    __shared__ float ws[8];
    if ((t & 31) == 0) ws[t >> 5] = s;
    __syncthreads();
    if (t == 0) {
        float tot = 0.f;
#pragma unroll
        for (int i = 0; i < 8; i++) tot += ws[i];
        out[LOSS_OFF] = g_loss * (1.0f / 8388608.0f);
        out[PERP_OFF] = expf(-tot);
    }
}

// ---------------------------------------------------------------------------
extern "C" void kernel_launch(void* const* d_in, const int* in_sizes, int n_in,
                              void* d_out, int out_size) {
    const float* x = (const float*)d_in[0];
    const float* w = (const float*)d_in[1];
    if (n_in >= 2 && in_sizes[0] == M_CB * D_DIM && in_sizes[1] == Q_ELEMS) {
        x = (const float*)d_in[1];
        w = (const float*)d_in[0];
    }
    float* out = (float*)d_out;

    cudaFuncSetAttribute(vq_main_kernel,
                         cudaFuncAttributeMaxDynamicSharedMemorySize, SM_TOTAL);

    // same launch order that successfully profiled vq_main last rounds
    prep_kernel<<<128, 256>>>(w);
    noop_kernel<<<1, 1>>>();
    noop_kernel<<<1, 1>>>();
    vq_main_kernel<<<BN_TOTAL / 64, 256, SM_TOTAL>>>(x, w, out);
    finalize_kernel<<<1, 256>>>(out);
}

// round 13
// speedup vs baseline: 1.0128x; 1.0128x over previous
#include <cuda_runtime.h>
#include <cuda_fp16.h>
#include <cstdint>

// VQ: B=16, N=4096, D=128, M=2048
// out layout (float32): quantized_st[8388608], loss[1], perp[1], indices[65536]

#define BN_TOTAL 65536
#define M_CB     2048
#define D_DIM    128
#define Q_ELEMS  8388608
#define LOSS_OFF 8388608
#define PERP_OFF 8388609
#define IDX_OFF  8388610

#define ROW_PITCH   272u                 // 136 fp16 per row (128 data + 8 pad)
#define SPLIT_BYTES (M_CB * ROW_PITCH)   // 557056 per split image
#define A_SPLIT     17408u               // 64 rows * 272 (per split)
#define B_SPLIT     17408u               // 64 rows * 272
#define B_HALF      8704u                // 32 rows * 272 (per group half)
#define B_BUF       34816u               // 2 splits (hi, mid)
#define NUM_NT      32

#define THRESH      2.0e-3f              // ~7x the rigorous approx-dist error bound
#define U64MAX      0xFFFFFFFFFFFFFFFFull

// SMEM map (bytes). 3 B buffers; A staging image OVERLAYS buf0 (same size):
// A is consumed into registers before the first B load lands.
#define SM_AB     0u                     // 3 bufs * 34816 = 104448
#define SM_L2Q    104448u                // 256
#define SM_CAND   104704u                // 64 rows * 4 u64 = 2048
#define SM_BEST   106752u                // 256
#define SM_WSUM   107008u                // 32
#define SM_TOTAL  107040u

__device__ __align__(256) float g_l2k[M_CB];
__device__ int   g_counts[M_CB];
__device__ float g_loss;
__device__ __align__(256) unsigned char g_wsplit[2u * SPLIT_BYTES];

// ---------------------------------------------------------------------------
__device__ __forceinline__ uint32_t smem_to_u32(const void* p) {
    uint32_t a;
    asm("{ .reg .u64 t; cvta.to.shared.u64 t, %1; cvt.u32.u64 %0, t; }"
        : "=r"(a) : "l"(p));
    return a;
}
__device__ __forceinline__ void cp16(uint32_t dst, const void* src) {
    asm volatile("cp.async.cg.shared.global [%0], [%1], 16;"
                 :: "r"(dst), "l"(src) : "memory");
}
__device__ __forceinline__ void cp_commit() {
    asm volatile("cp.async.commit_group;" ::: "memory");
}
__device__ __forceinline__ void cp_wait1() {
    asm volatile("cp.async.wait_group 1;" ::: "memory");
}
__device__ __forceinline__ void cp_wait0() {
    asm volatile("cp.async.wait_group 0;" ::: "memory");
}
__device__ __forceinline__ void barg(int id) {
    asm volatile("bar.sync %0, 128;" :: "r"(id) : "memory");
}
__device__ __forceinline__ void ldsm4(uint32_t* r, uint32_t addr) {
    asm volatile("ldmatrix.sync.aligned.m8n8.x4.shared.b16 {%0,%1,%2,%3}, [%4];"
                 : "=r"(r[0]), "=r"(r[1]), "=r"(r[2]), "=r"(r[3]) : "r"(addr));
}
__device__ __forceinline__ void mma_f16(float* d, const uint32_t* a, const uint32_t* b) {
    asm volatile(
        "mma.sync.aligned.m16n8k16.row.col.f32.f16.f16.f32 "
        "{%0,%1,%2,%3}, {%4,%5,%6,%7}, {%8,%9}, {%0,%1,%2,%3};"
        : "+f"(d[0]), "+f"(d[1]), "+f"(d[2]), "+f"(d[3])
        : "r"(a[0]), "r"(a[1]), "r"(a[2]), "r"(a[3]), "r"(b[0]), "r"(b[1]));
}
__device__ __forceinline__ void split2h(float v, __half& h, __half& m) {
    h = __float2half_rn(v);
    float r1 = __fsub_rn(v, __half2float(h));
    m = __float2half_rn(r1);
}
// branchless packed top-2: p = (float_bits << 32) | index.
// dists are all >> 0 so unsigned u64 order == (value, index) lexicographic.
__device__ __forceinline__ void t2upd(unsigned long long& b1, unsigned long long& b2,
                                      float v, unsigned n) {
    unsigned long long p =
        ((unsigned long long)__float_as_uint(v) << 32) | (unsigned long long)n;
    unsigned long long mx = p > b1 ? p : b1;
    b1 = p < b1 ? p : b1;
    b2 = mx < b2 ? mx : b2;
}
__device__ __forceinline__ unsigned long long shfl_xor_u64(unsigned long long v, int off) {
    uint32_t lo = (uint32_t)v, hi = (uint32_t)(v >> 32);
    lo = __shfl_xor_sync(0xffffffffu, lo, off);
    hi = __shfl_xor_sync(0xffffffffu, hi, off);
    return ((unsigned long long)hi << 32) | lo;
}

// ---------------------------------------------------------------------------
__global__ void noop_kernel() {}

// ---------------------------------------------------------------------------
// prep: codebook hi/mid fp16 splits into padded gmem images + ||k||^2 + zeroing
// ---------------------------------------------------------------------------
__global__ void prep_kernel(const float* __restrict__ w) {
    const int oct = blockIdx.x * 256 + threadIdx.x;   // 0..32767
    {
        int n = oct >> 4, k0 = (oct & 15) << 3;
        const float* src = w + (size_t)n * D_DIM + k0;
        __align__(16) __half hi[8], mi[8];
#pragma unroll
        for (int j = 0; j < 8; j++) split2h(src[j], hi[j], mi[j]);
        uint32_t off = (uint32_t)n * ROW_PITCH + (uint32_t)k0 * 2;
        *(uint4*)(g_wsplit + off)               = *(uint4*)hi;
        *(uint4*)(g_wsplit + SPLIT_BYTES + off) = *(uint4*)mi;
    }
    if (oct < M_CB) {
        const float* wr = w + (size_t)oct * D_DIM;
        float s = 0.f;
        for (int i = 0; i < D_DIM; i++)
            s = __fadd_rn(s, __fmul_rn(wr[i], wr[i]));   // strict sequential
        g_l2k[oct]    = s;
        g_counts[oct] = 0;
        if (oct == 0) g_loss = 0.f;
    }
}

// ---------------------------------------------------------------------------
// each 128-thread group loads ONLY its own 32-row half of a B tile
__device__ __forceinline__ void load_b_half(uint32_t sb, int buf, int nt,
                                            int grp, int gt) {
#pragma unroll
    for (int s = 0; s < 2; s++) {
        const unsigned char* src = g_wsplit + (size_t)s * SPLIT_BYTES
                                 + (size_t)nt * B_SPLIT + (size_t)grp * B_HALF;
        uint32_t dst = sb + SM_AB + (uint32_t)buf * B_BUF
                     + (uint32_t)s * B_SPLIT + (uint32_t)grp * B_HALF;
        for (int i = gt; i < (int)(B_HALF / 16); i += 128)
            cp16(dst + (uint32_t)i * 16u, src + (size_t)i * 16);
    }
}

__device__ __forceinline__ float exact_dist(const float* __restrict__ xrow,
                                            const float* __restrict__ w,
                                            int n, float l2q, float l2k) {
    const float4* wr = (const float4*)(w + (size_t)n * D_DIM);
    const float4* xr = (const float4*)xrow;
    float ps = 0.f;
#pragma unroll
    for (int i = 0; i < 32; i++) {
        float4 a = xr[i], b = wr[i];
        ps = __fmaf_rn(a.x, b.x, ps);
        ps = __fmaf_rn(a.y, b.y, ps);
        ps = __fmaf_rn(a.z, b.z, ps);
        ps = __fmaf_rn(a.w, b.w, ps);
    }
    return __fmaf_rn(-2.f, ps, __fadd_rn(l2q, l2k));
}

// ---------------------------------------------------------------------------
// main: M=64 query tile per CTA, 256 threads (8 warps, 4(M) x 2(N)),
// 2 CTAs/SM. Two INDEPENDENT half-CTA pipelines (wy groups) with named
// barriers; 3-stage cp.async (distance-2) B prefetch; A fragments
// register-resident; 3-pass fp16-split HMMA sweep; packed top-2; refine.
// ---------------------------------------------------------------------------
__global__ __launch_bounds__(256, 2)
void vq_main_kernel(const float* __restrict__ x, const float* __restrict__ w,
                    float* __restrict__ out)
{
    extern __shared__ char smem[];
    const uint32_t sb = smem_to_u32(smem);
    const int tid = threadIdx.x;
    const int wid = tid >> 5, l = tid & 31;
    const int wx = wid & 3, wy = wid >> 2;        // wx: M (4 x 16 rows), wy: N group
    const int lq = l >> 2, lr = l & 3;
    const int m0 = blockIdx.x * 64;
    const int grp = wy;                            // group id == tid>>7
    const int gt  = tid & 127;                     // thread id within group

    float* l2q_s  = (float*)(smem + SM_L2Q);
    unsigned long long* cand = (unsigned long long*)(smem + SM_CAND);  // [64][4]
    int*   best_s = (int*)  (smem + SM_BEST);
    float* wsum   = (float*)(smem + SM_WSUM);

    // ---- build A split images (hi/mid fp16) in buf0 region (overlay)
#pragma unroll
    for (int i = 0; i < 4; i++) {
        int idx = tid + (i << 8);               // 0..1023 octets (64 rows x 16)
        int r = idx >> 4, k0 = (idx & 15) << 3;
        const float4* src = (const float4*)(x + (size_t)(m0 + r) * D_DIM + k0);
        float4 v0 = src[0], v1 = src[1];
        float vv[8] = {v0.x, v0.y, v0.z, v0.w, v1.x, v1.y, v1.z, v1.w};
        __align__(16) __half hi[8], mi[8];
#pragma unroll
        for (int j = 0; j < 8; j++) split2h(vv[j], hi[j], mi[j]);
        uint32_t off = SM_AB + (uint32_t)r * ROW_PITCH + (uint32_t)k0 * 2;
        *(uint4*)(smem + off)           = *(uint4*)hi;
        *(uint4*)(smem + off + A_SPLIT) = *(uint4*)mi;
    }
    // ---- l2q per row: strict sequential fp32 (reference rounding)
    if (tid < 64) {
        const float* xr = x + (size_t)(m0 + tid) * D_DIM;
        float s = 0.f;
        for (int k = 0; k < D_DIM; k++)
            s = __fadd_rn(s, __fmul_rn(xr[k], xr[k]));
        l2q_s[tid] = s;
    }
    __syncthreads();     // A image visible

    // ---- load A fragments ONCE (register-resident: 2 splits x 8 chunks x 4)
    uint32_t aF[2][8][4];
    {
        uint32_t row = (uint32_t)(wx * 16) + (uint32_t)(l & 15);
        uint32_t kbl = (uint32_t)((l >> 4) & 1) * 16u;
        uint32_t base = sb + SM_AB + row * ROW_PITCH + kbl;
#pragma unroll
        for (int s = 0; s < 2; s++)
#pragma unroll
            for (int c = 0; c < 8; c++)
                ldsm4(aF[s][c], base + (uint32_t)s * A_SPLIT + (uint32_t)c * 32u);
    }
    float lqr[2];
    lqr[0] = l2q_s[wx * 16 + lq];
    lqr[1] = l2q_s[wx * 16 + lq + 8];
    __syncthreads();     // A image consumed -> buf0 free for B

    // prefetch tiles 0 (buf0) and 1 (buf1), per group half, separate groups
    load_b_half(sb, 0, 0, grp, gt);
    cp_commit();
    load_b_half(sb, 1, 1, grp, gt);
    cp_commit();

    // B lane base (within own group's half); buf offset added per tile
    uint32_t bBase;
    {
        uint32_t row = (uint32_t)(wy * 32) + (uint32_t)(l & 7) + (uint32_t)((l >> 4) & 1) * 8u;
        uint32_t kbl = (uint32_t)((l >> 3) & 1) * 16u;
        bBase = sb + SM_AB + row * ROW_PITCH + kbl;
    }

    unsigned long long t1[2] = {U64MAX, U64MAX};
    unsigned long long t2[2] = {U64MAX, U64MAX};

    for (int nt = 0; nt < NUM_NT; nt++) {
        if (nt < NUM_NT - 1) cp_wait1(); else cp_wait0();   // tile nt data done
        barg(1 + grp);        // group-local: data visible; group done with
                              // the buffer about to be overwritten below
        if (nt + 2 < NUM_NT) {
            load_b_half(sb, (nt + 2) % 3, nt + 2, grp, gt);
            cp_commit();
        }

        float acc[4][4];
#pragma unroll
        for (int n8 = 0; n8 < 4; n8++)
#pragma unroll
            for (int q = 0; q < 4; q++) acc[n8][q] = 0.f;

        const uint32_t bOff = (uint32_t)(nt % 3) * B_BUF;

#pragma unroll
        for (int c = 0; c < 8; c++) {
            const uint32_t kb = (uint32_t)c * 32u;
            uint32_t bF[2][2][4];    // [split][ni16][reg]
#pragma unroll
            for (int s = 0; s < 2; s++)
#pragma unroll
                for (int g = 0; g < 2; g++)
                    ldsm4(bF[s][g],
                          bBase + bOff + (uint32_t)s * B_SPLIT
                                + (uint32_t)g * (16u * ROW_PITCH) + kb);

            // passes: hh, hM, mH
            const int PA[3] = {0, 0, 1};
            const int PB[3] = {0, 1, 0};
#pragma unroll
            for (int p = 0; p < 3; p++)
#pragma unroll
                for (int n8 = 0; n8 < 4; n8++)
                    mma_f16(acc[n8], aF[PA[p]][c], &bF[PB[p]][n8 >> 1][(n8 & 1) * 2]);
        }

        // epilogue: packed top-2 (ascending index order); l2k via L1-resident LDG
#pragma unroll
        for (int n8 = 0; n8 < 4; n8++) {
            const int col0 = nt * 64 + wy * 32 + n8 * 8 + (lr << 1);
            const float2 lk = __ldg((const float2*)(g_l2k + col0));
            float v;
            v = __fmaf_rn(-2.f, acc[n8][0], __fadd_rn(lqr[0], lk.x));
            t2upd(t1[0], t2[0], v, (unsigned)col0);
            v = __fmaf_rn(-2.f, acc[n8][1], __fadd_rn(lqr[0], lk.y));
            t2upd(t1[0], t2[0], v, (unsigned)(col0 + 1));
            v = __fmaf_rn(-2.f, acc[n8][2], __fadd_rn(lqr[1], lk.x));
            t2upd(t1[1], t2[1], v, (unsigned)col0);
            v = __fmaf_rn(-2.f, acc[n8][3], __fadd_rn(lqr[1], lk.y));
            t2upd(t1[1], t2[1], v, (unsigned)(col0 + 1));
        }
        // no trailing barrier: next iteration's group barrier protects reuse
    }

    // ---- merge top-2 across the 4 lanes (lr) sharing each row
#pragma unroll
    for (int h = 0; h < 2; h++) {
        unsigned long long b1 = t1[h], b2 = t2[h];
#pragma unroll
        for (int off = 1; off <= 2; off <<= 1) {
            unsigned long long o1 = shfl_xor_u64(b1, off);
            unsigned long long o2 = shfl_xor_u64(b2, off);
            unsigned long long mx = b1 > o1 ? b1 : o1;
            b1 = b1 < o1 ? b1 : o1;
            unsigned long long mn2 = b2 < o2 ? b2 : o2;
            b2 = mn2 < mx ? mn2 : mx;
        }
        if (lr == 0) {
            int row = wx * 16 + h * 8 + lq;
            cand[row * 4 + wy * 2 + 0] = b1;
            cand[row * 4 + wy * 2 + 1] = b2;
        }
    }
    __syncthreads();    // both groups' cand slots visible

    // ---- per-row final scan + rare exact refine
    if (tid < 64) {
        unsigned long long b1 = U64MAX, b2 = U64MAX;
#pragma unroll
        for (int j = 0; j < 4; j++) {
            unsigned long long p = cand[tid * 4 + j];
            unsigned long long mx = p > b1 ? p : b1;
            b1 = p < b1 ? p : b1;
            b2 = mx < b2 ? mx : b2;
        }
        float v1 = __uint_as_float((uint32_t)(b1 >> 32));
        float v2 = __uint_as_float((uint32_t)(b2 >> 32));
        int best = (int)(uint32_t)(b1 & 0xFFFFFFFFu);
        if (v2 - v1 <= THRESH) {
            const float* xrow = x + (size_t)(m0 + tid) * D_DIM;
            const float l2q_r = l2q_s[tid];
            float bd = 3.0e38f;
            int   bi = 0x7fffffff;
#pragma unroll
            for (int j = 0; j < 4; j++) {
                unsigned long long p = cand[tid * 4 + j];
                float pv = __uint_as_float((uint32_t)(p >> 32));
                if (pv <= v1 + THRESH) {
                    int n = (int)(uint32_t)(p & 0xFFFFFFFFu);
                    float d = exact_dist(xrow, w, n, l2q_r, __ldg(g_l2k + n));
                    if (d < bd || (d == bd && n < bi)) { bd = d; bi = n; }
                }
            }
            best = bi;
        }
        best_s[tid] = best;
        atomicAdd(&g_counts[best], 1);
        out[IDX_OFF + m0 + tid] = (float)best;
    }
    __syncthreads();

    // ---- gather z, quantized_st = x + (z - x), loss partial (quarter-row/thread)
    {
        const int r  = tid >> 2;
        const int kb = (tid & 3) << 5;
        const int best = best_s[r];
        const float4* xr = (const float4*)(x + (size_t)(m0 + r) * D_DIM + kb);
        const float4* wz = (const float4*)(w + (size_t)best * D_DIM + kb);
        float4* oq = (float4*)(out + (size_t)(m0 + r) * D_DIM + kb);
        float lsum = 0.f;
#pragma unroll
        for (int i = 0; i < 8; i++) {
            float4 xv = xr[i], z = wz[i];
            float4 qv;
            qv.x = __fadd_rn(xv.x, __fsub_rn(z.x, xv.x));
            qv.y = __fadd_rn(xv.y, __fsub_rn(z.y, xv.y));
            qv.z = __fadd_rn(xv.z, __fsub_rn(z.z, xv.z));
            qv.w = __fadd_rn(xv.w, __fsub_rn(z.w, xv.w));
            oq[i] = qv;
            float d0 = __fsub_rn(qv.x, xv.x), d1 = __fsub_rn(qv.y, xv.y);
            float d2 = __fsub_rn(qv.z, xv.z), d3 = __fsub_rn(qv.w, xv.w);
            lsum += d0 * d0 + d1 * d1 + d2 * d2 + d3 * d3;
        }
#pragma unroll
        for (int o = 16; o > 0; o >>= 1)
            lsum += __shfl_down_sync(0xffffffffu, lsum, o);
        if ((tid & 31) == 0) wsum[wid] = lsum;
    }
    __syncthreads();
    if (tid == 0) {
        float s = 0.f;
#pragma unroll
        for (int i = 0; i < 8; i++) s += wsum[i];
        atomicAdd(&g_loss, s);
    }
}

// ---------------------------------------------------------------------------
// finalize: loss mean + perplexity
// ---------------------------------------------------------------------------
__global__ void finalize_kernel(float* __restrict__ out) {
    int t = threadIdx.x;
    float s = 0.f;
    for (int i = t; i < M_CB; i += 256) {
        float p = (float)g_counts[i] * (1.0f / 65536.0f);
        s += p * logf(p + 1e-10f);
    }
#pragma unroll
    for (int o = 16; o > 0; o >>= 1)
        s += __shfl_down_sync(0xffffffffu, s, o);
    __shared__ float ws[8];
    if ((t & 31) == 0) ws[t >> 5] = s;
    __syncthreads();
    if (t == 0) {
        float tot = 0.f;
#pragma unroll
        for (int i = 0; i < 8; i++) tot += ws[i];
        out[LOSS_OFF] = g_loss * (1.0f / 8388608.0f);
        out[PERP_OFF] = expf(-tot);
    }
}

// ---------------------------------------------------------------------------
extern "C" void kernel_launch(void* const* d_in, const int* in_sizes, int n_in,
                              void* d_out, int out_size) {
    const float* x = (const float*)d_in[0];
    const float* w = (const float*)d_in[1];
    if (n_in >= 2 && in_sizes[0] == M_CB * D_DIM && in_sizes[1] == Q_ELEMS) {
        x = (const float*)d_in[1];
        w = (const float*)d_in[0];
    }
    float* out = (float*)d_out;

    cudaFuncSetAttribute(vq_main_kernel,
                         cudaFuncAttributeMaxDynamicSharedMemorySize, SM_TOTAL);

    // same launch order that successfully profiled vq_main last rounds
    prep_kernel<<<128, 256>>>(w);
    noop_kernel<<<1, 1>>>();
    noop_kernel<<<1, 1>>>();
    vq_main_kernel<<<BN_TOTAL / 64, 256, SM_TOTAL>>>(x, w, out);
    finalize_kernel<<<1, 256>>>(out);
}

// round 14
// speedup vs baseline: 1.0537x; 1.0404x over previous
#include <cuda_runtime.h>
#include <cuda_fp16.h>
#include <cstdint>

// VQ: B=16, N=4096, D=128, M=2048
// out layout (float32): quantized_st[8388608], loss[1], perp[1], indices[65536]

#define BN_TOTAL 65536
#define M_CB     2048
#define D_DIM    128
#define Q_ELEMS  8388608
#define LOSS_OFF 8388608
#define PERP_OFF 8388609
#define IDX_OFF  8388610

#define ROW_PITCH   272u                 // 136 fp16 per row (128 data + 8 pad)
#define SPLIT_BYTES (M_CB * ROW_PITCH)   // 557056 per split image
#define A_SPLIT     17408u               // 64 rows * 272 (per split)
#define B_SPLIT     17408u               // 64 rows * 272
#define B_HALF      8704u                // 32 rows * 272 (per group half)
#define B_BUF       34816u               // 2 splits (hi, mid)
#define NUM_NT      32

#define THRESH      2.0e-3f              // ~7x the rigorous approx-dist error bound
#define U64MAX      0xFFFFFFFFFFFFFFFFull

// SMEM map (bytes). A staging image OVERLAYS B buf0 (same 34816 size):
// A is consumed into registers before the first B load lands.
#define SM_AB     0u                     // 2 B bufs * 34816 = 69632 (buf0 = A image first)
#define SM_L2K    69632u                 // 8192
#define SM_L2Q    77824u                 // 256
#define SM_CAND   78080u                 // 64 rows * 4 u64 = 2048
#define SM_BEST   80128u                 // 256
#define SM_WSUM   80384u                 // 32
#define SM_TOTAL  80416u

__device__ float g_l2k[M_CB];
__device__ int   g_counts[M_CB];
__device__ float g_loss;
__device__ __align__(256) unsigned char g_wsplit[2u * SPLIT_BYTES];

// ---------------------------------------------------------------------------
__device__ __forceinline__ uint32_t smem_to_u32(const void* p) {
    uint32_t a;
    asm("{ .reg .u64 t; cvta.to.shared.u64 t, %1; cvt.u32.u64 %0, t; }"
        : "=r"(a) : "l"(p));
    return a;
}
__device__ __forceinline__ void cp16(uint32_t dst, const void* src) {
    asm volatile("cp.async.cg.shared.global [%0], [%1], 16;"
                 :: "r"(dst), "l"(src) : "memory");
}
__device__ __forceinline__ void cp_commit() {
    asm volatile("cp.async.commit_group;" ::: "memory");
}
__device__ __forceinline__ void cp_wait0() {
    asm volatile("cp.async.wait_group 0;" ::: "memory");
}
__device__ __forceinline__ void barg(int id) {
    asm volatile("bar.sync %0, 128;" :: "r"(id) : "memory");
}
__device__ __forceinline__ void ldsm4(uint32_t* r, uint32_t addr) {
    asm volatile("ldmatrix.sync.aligned.m8n8.x4.shared.b16 {%0,%1,%2,%3}, [%4];"
                 : "=r"(r[0]), "=r"(r[1]), "=r"(r[2]), "=r"(r[3]) : "r"(addr));
}
__device__ __forceinline__ void mma_f16(float* d, const uint32_t* a, const uint32_t* b) {
    asm volatile(
        "mma.sync.aligned.m16n8k16.row.col.f32.f16.f16.f32 "
        "{%0,%1,%2,%3}, {%4,%5,%6,%7}, {%8,%9}, {%0,%1,%2,%3};"
        : "+f"(d[0]), "+f"(d[1]), "+f"(d[2]), "+f"(d[3])
        : "r"(a[0]), "r"(a[1]), "r"(a[2]), "r"(a[3]), "r"(b[0]), "r"(b[1]));
}
__device__ __forceinline__ void split2h(float v, __half& h, __half& m) {
    h = __float2half_rn(v);
    float r1 = __fsub_rn(v, __half2float(h));
    m = __float2half_rn(r1);
}
// branchless packed top-2: p = (float_bits << 32) | index.
// dists are all >> 0 so unsigned u64 order == (value, index) lexicographic.
// t2upd is a commutative min/2nd-min lattice op -> tile ORDER-INDEPENDENT.
__device__ __forceinline__ void t2upd(unsigned long long& b1, unsigned long long& b2,
                                      float v, unsigned n) {
    unsigned long long p =
        ((unsigned long long)__float_as_uint(v) << 32) | (unsigned long long)n;
    unsigned long long mx = p > b1 ? p : b1;
    b1 = p < b1 ? p : b1;
    b2 = mx < b2 ? mx : b2;
}
__device__ __forceinline__ unsigned long long shfl_xor_u64(unsigned long long v, int off) {
    uint32_t lo = (uint32_t)v, hi = (uint32_t)(v >> 32);
    lo = __shfl_xor_sync(0xffffffffu, lo, off);
    hi = __shfl_xor_sync(0xffffffffu, hi, off);
    return ((unsigned long long)hi << 32) | lo;
}

// ---------------------------------------------------------------------------
// prep: codebook hi/mid fp16 splits into padded gmem images + ||k||^2 + zeroing
// ---------------------------------------------------------------------------
__global__ void prep_kernel(const float* __restrict__ w) {
    const int oct = blockIdx.x * 256 + threadIdx.x;   // 0..32767
    {
        int n = oct >> 4, k0 = (oct & 15) << 3;
        const float* src = w + (size_t)n * D_DIM + k0;
        __align__(16) __half hi[8], mi[8];
#pragma unroll
        for (int j = 0; j < 8; j++) split2h(src[j], hi[j], mi[j]);
        uint32_t off = (uint32_t)n * ROW_PITCH + (uint32_t)k0 * 2;
        *(uint4*)(g_wsplit + off)               = *(uint4*)hi;
        *(uint4*)(g_wsplit + SPLIT_BYTES + off) = *(uint4*)mi;
    }
    if (oct < M_CB) {
        const float* wr = w + (size_t)oct * D_DIM;
        float s = 0.f;
        for (int i = 0; i < D_DIM; i++)
            s = __fadd_rn(s, __fmul_rn(wr[i], wr[i]));   // strict sequential
        g_l2k[oct]    = s;
        g_counts[oct] = 0;
        if (oct == 0) g_loss = 0.f;
    }
}

// ---------------------------------------------------------------------------
// each 128-thread group loads ONLY its own 32-row half of a B tile
__device__ __forceinline__ void load_b_half(uint32_t sb, int buf, int nt,
                                            int grp, int gt) {
#pragma unroll
    for (int s = 0; s < 2; s++) {
        const unsigned char* src = g_wsplit + (size_t)s * SPLIT_BYTES
                                 + (size_t)nt * B_SPLIT + (size_t)grp * B_HALF;
        uint32_t dst = sb + SM_AB + (uint32_t)buf * B_BUF
                     + (uint32_t)s * B_SPLIT + (uint32_t)grp * B_HALF;
        for (int i = gt; i < (int)(B_HALF / 16); i += 128)
            cp16(dst + (uint32_t)i * 16u, src + (size_t)i * 16);
    }
}

__device__ __forceinline__ float exact_dist(const float* __restrict__ xrow,
                                            const float* __restrict__ w,
                                            int n, float l2q, float l2k) {
    const float4* wr = (const float4*)(w + (size_t)n * D_DIM);
    const float4* xr = (const float4*)xrow;
    float ps = 0.f;
#pragma unroll
    for (int i = 0; i < 32; i++) {
        float4 a = xr[i], b = wr[i];
        ps = __fmaf_rn(a.x, b.x, ps);
        ps = __fmaf_rn(a.y, b.y, ps);
        ps = __fmaf_rn(a.z, b.z, ps);
        ps = __fmaf_rn(a.w, b.w, ps);
    }
    return __fmaf_rn(-2.f, ps, __fadd_rn(l2q, l2k));
}

// ---------------------------------------------------------------------------
// main: M=64 query tile per CTA, 256 threads (8 warps, 4(M) x 2(N)),
// 2 CTAs/SM. Two independent half-CTA pipelines (wy groups) with named
// barriers; 2-buffer cp.async prefetch; CTA-parity tile-phase stagger;
// A fragments register-resident; 3-pass fp16-split HMMA sweep; packed
// top-2; rare exact fp32 refine; epilogue.
// ---------------------------------------------------------------------------
__global__ __launch_bounds__(256, 2)
void vq_main_kernel(const float* __restrict__ x, const float* __restrict__ w,
                    float* __restrict__ out)
{
    extern __shared__ char smem[];
    const uint32_t sb = smem_to_u32(smem);
    const int tid = threadIdx.x;
    const int wid = tid >> 5, l = tid & 31;
    const int wx = wid & 3, wy = wid >> 2;        // wx: M (4 x 16 rows), wy: N group
    const int lq = l >> 2, lr = l & 3;
    const int m0 = blockIdx.x * 64;
    const int grp = wy;                            // group id == tid>>7
    const int gt  = tid & 127;                     // thread id within group
    const int phase = (blockIdx.x & 1) << 4;       // co-resident CTA stagger

    float* l2k_s  = (float*)(smem + SM_L2K);
    float* l2q_s  = (float*)(smem + SM_L2Q);
    unsigned long long* cand = (unsigned long long*)(smem + SM_CAND);  // [64][4]
    int*   best_s = (int*)  (smem + SM_BEST);
    float* wsum   = (float*)(smem + SM_WSUM);

    // ---- build A split images (hi/mid fp16) in B-buf0 region (overlay)
#pragma unroll
    for (int i = 0; i < 4; i++) {
        int idx = tid + (i << 8);               // 0..1023 octets (64 rows x 16)
        int r = idx >> 4, k0 = (idx & 15) << 3;
        const float4* src = (const float4*)(x + (size_t)(m0 + r) * D_DIM + k0);
        float4 v0 = src[0], v1 = src[1];
        float vv[8] = {v0.x, v0.y, v0.z, v0.w, v1.x, v1.y, v1.z, v1.w};
        __align__(16) __half hi[8], mi[8];
#pragma unroll
        for (int j = 0; j < 8; j++) split2h(vv[j], hi[j], mi[j]);
        uint32_t off = SM_AB + (uint32_t)r * ROW_PITCH + (uint32_t)k0 * 2;
        *(uint4*)(smem + off)           = *(uint4*)hi;
        *(uint4*)(smem + off + A_SPLIT) = *(uint4*)mi;
    }
    // ---- stage l2k (512 float4 = 2048 floats)
    ((float4*)l2k_s)[tid]       = ((const float4*)g_l2k)[tid];
    ((float4*)l2k_s)[tid + 256] = ((const float4*)g_l2k)[tid + 256];
    // ---- l2q per row: strict sequential fp32 (reference rounding)
    if (tid < 64) {
        const float* xr = x + (size_t)(m0 + tid) * D_DIM;
        float s = 0.f;
        for (int k = 0; k < D_DIM; k++)
            s = __fadd_rn(s, __fmul_rn(xr[k], xr[k]));
        l2q_s[tid] = s;
    }
    __syncthreads();     // A image visible

    // ---- load A fragments ONCE (register-resident: 2 splits x 8 chunks x 4)
    uint32_t aF[2][8][4];
    {
        uint32_t row = (uint32_t)(wx * 16) + (uint32_t)(l & 15);
        uint32_t kbl = (uint32_t)((l >> 4) & 1) * 16u;
        uint32_t base = sb + SM_AB + row * ROW_PITCH + kbl;
#pragma unroll
        for (int s = 0; s < 2; s++)
#pragma unroll
            for (int c = 0; c < 8; c++)
                ldsm4(aF[s][c], base + (uint32_t)s * A_SPLIT + (uint32_t)c * 32u);
    }
    float lqr[2];
    lqr[0] = l2q_s[wx * 16 + lq];
    lqr[1] = l2q_s[wx * 16 + lq + 8];
    __syncthreads();     // A image consumed -> buf0 free for B

    // first B tile (phase-staggered) into buf0, per group half
    load_b_half(sb, 0, phase, grp, gt);
    cp_commit();

    // B lane base (within own group's half); buf offset added per tile
    uint32_t bBase;
    {
        uint32_t row = (uint32_t)(wy * 32) + (uint32_t)(l & 7) + (uint32_t)((l >> 4) & 1) * 8u;
        uint32_t kbl = (uint32_t)((l >> 3) & 1) * 16u;
        bBase = sb + SM_AB + row * ROW_PITCH + kbl;
    }

    unsigned long long t1[2] = {U64MAX, U64MAX};
    unsigned long long t2[2] = {U64MAX, U64MAX};

    for (int it = 0; it < NUM_NT; it++) {
        const int nt = (it + phase) & 31;          // actual tile id
        cp_wait0();          // this group's tile it arrived
        barg(1 + grp);       // group-local: data visible; group done with
                             // the buffer about to be overwritten below
        if (it + 1 < NUM_NT) {
            load_b_half(sb, (it + 1) & 1, (nt + 1) & 31, grp, gt);
            cp_commit();
        }

        float acc[4][4];
#pragma unroll
        for (int n8 = 0; n8 < 4; n8++)
#pragma unroll
            for (int q = 0; q < 4; q++) acc[n8][q] = 0.f;

        const uint32_t bOff = (uint32_t)(it & 1) * B_BUF;

#pragma unroll
        for (int c = 0; c < 8; c++) {
            const uint32_t kb = (uint32_t)c * 32u;
            uint32_t bF[2][2][4];    // [split][ni16][reg]
#pragma unroll
            for (int s = 0; s < 2; s++)
#pragma unroll
                for (int g = 0; g < 2; g++)
                    ldsm4(bF[s][g],
                          bBase + bOff + (uint32_t)s * B_SPLIT
                                + (uint32_t)g * (16u * ROW_PITCH) + kb);

            // passes: hh, hM, mH
            const int PA[3] = {0, 0, 1};
            const int PB[3] = {0, 1, 0};
#pragma unroll
            for (int p = 0; p < 3; p++)
#pragma unroll
                for (int n8 = 0; n8 < 4; n8++)
                    mma_f16(acc[n8], aF[PA[p]][c], &bF[PB[p]][n8 >> 1][(n8 & 1) * 2]);
        }

        // epilogue: packed top-2 (order-independent lattice op)
#pragma unroll
        for (int n8 = 0; n8 < 4; n8++) {
            const int col0 = nt * 64 + wy * 32 + n8 * 8 + (lr << 1);
            const float2 lk = *(const float2*)(l2k_s + col0);
            float v;
            v = __fmaf_rn(-2.f, acc[n8][0], __fadd_rn(lqr[0], lk.x));
            t2upd(t1[0], t2[0], v, (unsigned)col0);
            v = __fmaf_rn(-2.f, acc[n8][1], __fadd_rn(lqr[0], lk.y));
            t2upd(t1[0], t2[0], v, (unsigned)(col0 + 1));
            v = __fmaf_rn(-2.f, acc[n8][2], __fadd_rn(lqr[1], lk.x));
            t2upd(t1[1], t2[1], v, (unsigned)col0);
            v = __fmaf_rn(-2.f, acc[n8][3], __fadd_rn(lqr[1], lk.y));
            t2upd(t1[1], t2[1], v, (unsigned)(col0 + 1));
        }
        // no trailing barrier: next iteration's group barrier protects reuse
    }

    // ---- merge top-2 across the 4 lanes (lr) sharing each row
#pragma unroll
    for (int h = 0; h < 2; h++) {
        unsigned long long b1 = t1[h], b2 = t2[h];
#pragma unroll
        for (int off = 1; off <= 2; off <<= 1) {
            unsigned long long o1 = shfl_xor_u64(b1, off);
            unsigned long long o2 = shfl_xor_u64(b2, off);
            unsigned long long mx = b1 > o1 ? b1 : o1;
            b1 = b1 < o1 ? b1 : o1;
            unsigned long long mn2 = b2 < o2 ? b2 : o2;
            b2 = mn2 < mx ? mn2 : mx;
        }
        if (lr == 0) {
            int row = wx * 16 + h * 8 + lq;
            cand[row * 4 + wy * 2 + 0] = b1;
            cand[row * 4 + wy * 2 + 1] = b2;
        }
    }
    __syncthreads();    // both groups' cand slots visible

    // ---- per-row final scan + rare exact refine
    if (tid < 64) {
        unsigned long long b1 = U64MAX, b2 = U64MAX;
#pragma unroll
        for (int j = 0; j < 4; j++) {
            unsigned long long p = cand[tid * 4 + j];
            unsigned long long mx = p > b1 ? p : b1;
            b1 = p < b1 ? p : b1;
            b2 = mx < b2 ? mx : b2;
        }
        float v1 = __uint_as_float((uint32_t)(b1 >> 32));
        float v2 = __uint_as_float((uint32_t)(b2 >> 32));
        int best = (int)(uint32_t)(b1 & 0xFFFFFFFFu);
        if (v2 - v1 <= THRESH) {
            const float* xrow = x + (size_t)(m0 + tid) * D_DIM;
            const float l2q_r = l2q_s[tid];
            float bd = 3.0e38f;
            int   bi = 0x7fffffff;
#pragma unroll
            for (int j = 0; j < 4; j++) {
                unsigned long long p = cand[tid * 4 + j];
                float pv = __uint_as_float((uint32_t)(p >> 32));
                if (pv <= v1 + THRESH) {
                    int n = (int)(uint32_t)(p & 0xFFFFFFFFu);
                    float d = exact_dist(xrow, w, n, l2q_r, l2k_s[n]);
                    if (d < bd || (d == bd && n < bi)) { bd = d; bi = n; }
                }
            }
            best = bi;
        }
        best_s[tid] = best;
        atomicAdd(&g_counts[best], 1);
        out[IDX_OFF + m0 + tid] = (float)best;
    }
    __syncthreads();

    // ---- gather z, quantized_st = x + (z - x), loss partial (quarter-row/thread)
    {
        const int r  = tid >> 2;
        const int kb = (tid & 3) << 5;
        const int best = best_s[r];
        const float4* xr = (const float4*)(x + (size_t)(m0 + r) * D_DIM + kb);
        const float4* wz = (const float4*)(w + (size_t)best * D_DIM + kb);
        float4* oq = (float4*)(out + (size_t)(m0 + r) * D_DIM + kb);
        float lsum = 0.f;
#pragma unroll
        for (int i = 0; i < 8; i++) {
            float4 xv = xr[i], z = wz[i];
            float4 qv;
            qv.x = __fadd_rn(xv.x, __fsub_rn(z.x, xv.x));
            qv.y = __fadd_rn(xv.y, __fsub_rn(z.y, xv.y));
            qv.z = __fadd_rn(xv.z, __fsub_rn(z.z, xv.z));
            qv.w = __fadd_rn(xv.w, __fsub_rn(z.w, xv.w));
            oq[i] = qv;
            float d0 = __fsub_rn(qv.x, xv.x), d1 = __fsub_rn(qv.y, xv.y);
            float d2 = __fsub_rn(qv.z, xv.z), d3 = __fsub_rn(qv.w, xv.w);
            lsum += d0 * d0 + d1 * d1 + d2 * d2 + d3 * d3;
        }
#pragma unroll
        for (int o = 16; o > 0; o >>= 1)
            lsum += __shfl_down_sync(0xffffffffu, lsum, o);
        if ((tid & 31) == 0) wsum[wid] = lsum;
    }
    __syncthreads();
    if (tid == 0) {
        float s = 0.f;
#pragma unroll
        for (int i = 0; i < 8; i++) s += wsum[i];
        atomicAdd(&g_loss, s);
    }
}

// ---------------------------------------------------------------------------
// finalize: loss mean + perplexity
// ---------------------------------------------------------------------------
__global__ void finalize_kernel(float* __restrict__ out) {
    int t = threadIdx.x;
    float s = 0.f;
    for (int i = t; i < M_CB; i += 256) {
        float p = (float)g_counts[i] * (1.0f / 65536.0f);
        s += p * logf(p + 1e-10f);
    }
#pragma unroll
    for (int o = 16; o > 0; o >>= 1)
        s += __shfl_down_sync(0xffffffffu, s, o);
    __shared__ float ws[8];
    if ((t & 31) == 0) ws[t >> 5] = s;
    __syncthreads();
    if (t == 0) {
        float tot = 0.f;
#pragma unroll
        for (int i = 0; i < 8; i++) tot += ws[i];
        out[LOSS_OFF] = g_loss * (1.0f / 8388608.0f);
        out[PERP_OFF] = expf(-tot);
    }
}

// ---------------------------------------------------------------------------
extern "C" void kernel_launch(void* const* d_in, const int* in_sizes, int n_in,
                              void* d_out, int out_size) {
    const float* x = (const float*)d_in[0];
    const float* w = (const float*)d_in[1];
    if (n_in >= 2 && in_sizes[0] == M_CB * D_DIM && in_sizes[1] == Q_ELEMS) {
        x = (const float*)d_in[1];
        w = (const float*)d_in[0];
    }
    float* out = (float*)d_out;

    cudaFuncSetAttribute(vq_main_kernel,
                         cudaFuncAttributeMaxDynamicSharedMemorySize, SM_TOTAL);

    prep_kernel<<<128, 256>>>(w);
    vq_main_kernel<<<BN_TOTAL / 64, 256, SM_TOTAL>>>(x, w, out);
    finalize_kernel<<<1, 256>>>(out);
}

// round 15
// speedup vs baseline: 1.0648x; 1.0105x over previous
#include <cuda_runtime.h>
#include <cuda_fp16.h>
#include <cstdint>

// VQ: B=16, N=4096, D=128, M=2048
// out layout (float32): quantized_st[8388608], loss[1], perp[1], indices[65536]

#define BN_TOTAL 65536
#define M_CB     2048
#define D_DIM    128
#define Q_ELEMS  8388608
#define LOSS_OFF 8388608
#define PERP_OFF 8388609
#define IDX_OFF  8388610

#define ROW_PITCH   272u                 // 136 fp16 per row (128 data + 8 pad)
#define SPLIT_BYTES (M_CB * ROW_PITCH)   // 557056 (hi split image only)
#define B_SPLIT     17408u               // 64 rows * 272
#define B_HALF      8704u                // 32 rows * 272 (per group half)
#define B_BUF       17408u               // hi split only
#define NUM_NT      32

#define MARGIN      0.02f                // ~18 sigma of hh-only approx dist error
#define U64MAX      0xFFFFFFFFFFFFFFFFull

// SMEM map (bytes). A hi image OVERLAYS B buf0 (same 17408 size).
#define SM_AB     0u                     // 2 B bufs * 17408 = 34816
#define SM_L2K    34816u                 // 8192
#define SM_L2Q    43008u                 // 256
#define SM_CAND   43264u                 // 64 rows * 32 u64 = 16384
#define SM_BEST   59648u                 // 256
#define SM_WSUM   59904u                 // 32
#define SM_TOTAL  59936u

__device__ float g_l2k[M_CB];
__device__ int   g_counts[M_CB];
__device__ float g_loss;
__device__ __align__(256) unsigned char g_wsplit[SPLIT_BYTES];

// ---------------------------------------------------------------------------
__device__ __forceinline__ uint32_t smem_to_u32(const void* p) {
    uint32_t a;
    asm("{ .reg .u64 t; cvta.to.shared.u64 t, %1; cvt.u32.u64 %0, t; }"
        : "=r"(a) : "l"(p));
    return a;
}
__device__ __forceinline__ void cp16(uint32_t dst, const void* src) {
    asm volatile("cp.async.cg.shared.global [%0], [%1], 16;"
                 :: "r"(dst), "l"(src) : "memory");
}
__device__ __forceinline__ void cp_commit() {
    asm volatile("cp.async.commit_group;" ::: "memory");
}
__device__ __forceinline__ void cp_wait0() {
    asm volatile("cp.async.wait_group 0;" ::: "memory");
}
__device__ __forceinline__ void barg(int id) {
    asm volatile("bar.sync %0, 128;" :: "r"(id) : "memory");
}
__device__ __forceinline__ void ldsm4(uint32_t* r, uint32_t addr) {
    asm volatile("ldmatrix.sync.aligned.m8n8.x4.shared.b16 {%0,%1,%2,%3}, [%4];"
                 : "=r"(r[0]), "=r"(r[1]), "=r"(r[2]), "=r"(r[3]) : "r"(addr));
}
__device__ __forceinline__ void mma_f16(float* d, const uint32_t* a, const uint32_t* b) {
    asm volatile(
        "mma.sync.aligned.m16n8k16.row.col.f32.f16.f16.f32 "
        "{%0,%1,%2,%3}, {%4,%5,%6,%7}, {%8,%9}, {%0,%1,%2,%3};"
        : "+f"(d[0]), "+f"(d[1]), "+f"(d[2]), "+f"(d[3])
        : "r"(a[0]), "r"(a[1]), "r"(a[2]), "r"(a[3]), "r"(b[0]), "r"(b[1]));
}
// branchless packed top-4 insert: p = (float_bits << 32) | index.
// dists are all >> 0 so unsigned u64 order == (value, index) lexicographic.
__device__ __forceinline__ void t4ins(unsigned long long* t, unsigned long long p) {
    unsigned long long a0 = p  < t[0] ? p    : t[0];
    unsigned long long b0 = p  < t[0] ? t[0] : p;
    t[0] = a0;
    unsigned long long a1 = b0 < t[1] ? b0   : t[1];
    unsigned long long b1 = b0 < t[1] ? t[1] : b0;
    t[1] = a1;
    unsigned long long a2 = b1 < t[2] ? b1   : t[2];
    unsigned long long b2 = b1 < t[2] ? t[2] : b1;
    t[2] = a2;
    t[3] = b2 < t[3] ? b2 : t[3];
}

// ---------------------------------------------------------------------------
// prep: codebook hi fp16 image + ||k||^2 (strict sequential, spread across
// all blocks) + zeroing
// ---------------------------------------------------------------------------
__global__ void prep_kernel(const float* __restrict__ w) {
    const int oct = blockIdx.x * 256 + threadIdx.x;   // 0..32767
    {
        int n = oct >> 4, k0 = (oct & 15) << 3;
        const float* src = w + (size_t)n * D_DIM + k0;
        __align__(16) __half hi[8];
#pragma unroll
        for (int j = 0; j < 8; j++) hi[j] = __float2half_rn(src[j]);
        uint32_t off = (uint32_t)n * ROW_PITCH + (uint32_t)k0 * 2;
        *(uint4*)(g_wsplit + off) = *(uint4*)hi;
    }
    // l2k: 16 rows per block, spread over all 128 blocks (same per-row math)
    if (threadIdx.x < 16) {
        int row = blockIdx.x * 16 + threadIdx.x;
        const float* wr = w + (size_t)row * D_DIM;
        float s = 0.f;
        for (int i = 0; i < D_DIM; i++)
            s = __fadd_rn(s, __fmul_rn(wr[i], wr[i]));   // strict sequential
        g_l2k[row] = s;
    }
    if (oct < M_CB) g_counts[oct] = 0;
    if (oct == 0)   g_loss = 0.f;
}

// ---------------------------------------------------------------------------
// each 128-thread group loads ONLY its own 32-row half of a B tile (hi split)
__device__ __forceinline__ void load_b_half(uint32_t sb, int buf, int nt,
                                            int grp, int gt) {
    const unsigned char* src = g_wsplit + (size_t)nt * B_SPLIT + (size_t)grp * B_HALF;
    uint32_t dst = sb + SM_AB + (uint32_t)buf * B_BUF + (uint32_t)grp * B_HALF;
    for (int i = gt; i < (int)(B_HALF / 16); i += 128)
        cp16(dst + (uint32_t)i * 16u, src + (size_t)i * 16);
}

__device__ __forceinline__ float exact_dist(const float* __restrict__ xrow,
                                            const float* __restrict__ w,
                                            int n, float l2q, float l2k) {
    const float4* wr = (const float4*)(w + (size_t)n * D_DIM);
    const float4* xr = (const float4*)xrow;
    float ps = 0.f;
#pragma unroll
    for (int i = 0; i < 32; i++) {
        float4 a = xr[i], b = wr[i];
        ps = __fmaf_rn(a.x, b.x, ps);
        ps = __fmaf_rn(a.y, b.y, ps);
        ps = __fmaf_rn(a.z, b.z, ps);
        ps = __fmaf_rn(a.w, b.w, ps);
    }
    return __fmaf_rn(-2.f, ps, __fadd_rn(l2q, l2k));
}

// ---------------------------------------------------------------------------
// main: M=64 query tile per CTA, 256 threads (8 warps, 4(M) x 2(N)),
// 2 CTAs/SM. hh-only fp16 HMMA sweep (1 pass) with per-thread top-4
// capture per row-half; exact fp32 refine for near rows; epilogue.
// ---------------------------------------------------------------------------
__global__ __launch_bounds__(256, 2)
void vq_main_kernel(const float* __restrict__ x, const float* __restrict__ w,
                    float* __restrict__ out)
{
    extern __shared__ char smem[];
    const uint32_t sb = smem_to_u32(smem);
    const int tid = threadIdx.x;
    const int wid = tid >> 5, l = tid & 31;
    const int wx = wid & 3, wy = wid >> 2;        // wx: M (4 x 16 rows), wy: N group
    const int lq = l >> 2, lr = l & 3;
    const int m0 = blockIdx.x * 64;
    const int grp = wy;                            // group id == tid>>7
    const int gt  = tid & 127;                     // thread id within group
    const int phase = (blockIdx.x & 1) << 4;       // co-resident CTA stagger

    float* l2k_s  = (float*)(smem + SM_L2K);
    float* l2q_s  = (float*)(smem + SM_L2Q);
    unsigned long long* cand = (unsigned long long*)(smem + SM_CAND);  // [64][32]
    int*   best_s = (int*)  (smem + SM_BEST);
    float* wsum   = (float*)(smem + SM_WSUM);

    // ---- build A hi image (fp16) in B-buf0 region (overlay)
#pragma unroll
    for (int i = 0; i < 4; i++) {
        int idx = tid + (i << 8);               // 0..1023 octets (64 rows x 16)
        int r = idx >> 4, k0 = (idx & 15) << 3;
        const float4* src = (const float4*)(x + (size_t)(m0 + r) * D_DIM + k0);
        float4 v0 = src[0], v1 = src[1];
        float vv[8] = {v0.x, v0.y, v0.z, v0.w, v1.x, v1.y, v1.z, v1.w};
        __align__(16) __half hi[8];
#pragma unroll
        for (int j = 0; j < 8; j++) hi[j] = __float2half_rn(vv[j]);
        uint32_t off = SM_AB + (uint32_t)r * ROW_PITCH + (uint32_t)k0 * 2;
        *(uint4*)(smem + off) = *(uint4*)hi;
    }
    // ---- stage l2k (512 float4 = 2048 floats)
    ((float4*)l2k_s)[tid]       = ((const float4*)g_l2k)[tid];
    ((float4*)l2k_s)[tid + 256] = ((const float4*)g_l2k)[tid + 256];
    // ---- l2q per row: strict sequential fp32 (reference rounding)
    if (tid < 64) {
        const float* xr = x + (size_t)(m0 + tid) * D_DIM;
        float s = 0.f;
        for (int k = 0; k < D_DIM; k++)
            s = __fadd_rn(s, __fmul_rn(xr[k], xr[k]));
        l2q_s[tid] = s;
    }
    __syncthreads();     // A image visible

    // ---- load A fragments ONCE (register-resident: 8 chunks x 4 regs)
    uint32_t aF[8][4];
    {
        uint32_t row = (uint32_t)(wx * 16) + (uint32_t)(l & 15);
        uint32_t kbl = (uint32_t)((l >> 4) & 1) * 16u;
        uint32_t base = sb + SM_AB + row * ROW_PITCH + kbl;
#pragma unroll
        for (int c = 0; c < 8; c++)
            ldsm4(aF[c], base + (uint32_t)c * 32u);
    }
    float lqr[2];
    lqr[0] = l2q_s[wx * 16 + lq];
    lqr[1] = l2q_s[wx * 16 + lq + 8];
    __syncthreads();     // A image consumed -> buf0 free for B

    // first B tile (phase-staggered) into buf0, per group half
    load_b_half(sb, 0, phase, grp, gt);
    cp_commit();

    // B lane base (within own group's half); buf offset added per tile
    uint32_t bBase;
    {
        uint32_t row = (uint32_t)(wy * 32) + (uint32_t)(l & 7) + (uint32_t)((l >> 4) & 1) * 8u;
        uint32_t kbl = (uint32_t)((l >> 3) & 1) * 16u;
        bBase = sb + SM_AB + row * ROW_PITCH + kbl;
    }

    // per-thread top-4 per row-half
    unsigned long long t4[2][4];
#pragma unroll
    for (int h = 0; h < 2; h++)
#pragma unroll
        for (int j = 0; j < 4; j++) t4[h][j] = U64MAX;
    float f4[2] = {3.0e38f, 3.0e38f};   // fp32 shadow of 4th-best values

    for (int it = 0; it < NUM_NT; it++) {
        const int nt = (it + phase) & 31;          // actual tile id
        cp_wait0();          // this group's tile it arrived
        barg(1 + grp);       // group-local: data visible; group done with
                             // the buffer about to be overwritten below
        if (it + 1 < NUM_NT) {
            load_b_half(sb, (it + 1) & 1, (nt + 1) & 31, grp, gt);
            cp_commit();
        }

        float acc[4][4];
#pragma unroll
        for (int n8 = 0; n8 < 4; n8++)
#pragma unroll
            for (int q = 0; q < 4; q++) acc[n8][q] = 0.f;

        const uint32_t bOff = (uint32_t)(it & 1) * B_BUF;

#pragma unroll
        for (int c = 0; c < 8; c++) {
            const uint32_t kb = (uint32_t)c * 32u;
            uint32_t bF[2][4];    // [ni16][reg]
#pragma unroll
            for (int g = 0; g < 2; g++)
                ldsm4(bF[g], bBase + bOff + (uint32_t)g * (16u * ROW_PITCH) + kb);
#pragma unroll
            for (int n8 = 0; n8 < 4; n8++)
                mma_f16(acc[n8], aF[c], &bF[n8 >> 1][(n8 & 1) * 2]);
        }

        // epilogue: 16 dists -> per-half tile-min guard -> rare top-4 insert.
        // Skip is exact: all v > f4 strictly implies every packed key > t[3]
        // (positive-float bit monotonicity) -> inserts were no-ops.
        {
            float vv0[8], vv1[8];
#pragma unroll
            for (int n8 = 0; n8 < 4; n8++) {
                const int col0 = nt * 64 + wy * 32 + n8 * 8 + (lr << 1);
                const float2 lk = *(const float2*)(l2k_s + col0);
                vv0[n8 * 2 + 0] = __fmaf_rn(-2.f, acc[n8][0], __fadd_rn(lqr[0], lk.x));
                vv0[n8 * 2 + 1] = __fmaf_rn(-2.f, acc[n8][1], __fadd_rn(lqr[0], lk.y));
                vv1[n8 * 2 + 0] = __fmaf_rn(-2.f, acc[n8][2], __fadd_rn(lqr[1], lk.x));
                vv1[n8 * 2 + 1] = __fmaf_rn(-2.f, acc[n8][3], __fadd_rn(lqr[1], lk.y));
            }
            float tm0 = vv0[0], tm1 = vv1[0];
#pragma unroll
            for (int j = 1; j < 8; j++) {
                tm0 = fminf(tm0, vv0[j]);
                tm1 = fminf(tm1, vv1[j]);
            }
            const int base = nt * 64 + wy * 32 + (lr << 1);
            if (tm0 <= f4[0]) {
#pragma unroll
                for (int j = 0; j < 8; j++) {
                    unsigned n = (unsigned)(base + ((j >> 1) << 3) + (j & 1));
                    unsigned long long p =
                        ((unsigned long long)__float_as_uint(vv0[j]) << 32) | n;
                    t4ins(t4[0], p);
                }
                f4[0] = __uint_as_float((uint32_t)(t4[0][3] >> 32));
            }
            if (tm1 <= f4[1]) {
#pragma unroll
                for (int j = 0; j < 8; j++) {
                    unsigned n = (unsigned)(base + ((j >> 1) << 3) + (j & 1));
                    unsigned long long p =
                        ((unsigned long long)__float_as_uint(vv1[j]) << 32) | n;
                    t4ins(t4[1], p);
                }
                f4[1] = __uint_as_float((uint32_t)(t4[1][3] >> 32));
            }
        }
        // no trailing barrier: next iteration's group barrier protects reuse
    }

    // ---- write per-thread top-4 candidates (no lane merge: keep all 32/row)
#pragma unroll
    for (int h = 0; h < 2; h++) {
        int row = wx * 16 + h * 8 + lq;
        unsigned long long* dst = cand + row * 32 + wy * 16 + lr * 4;
#pragma unroll
        for (int j = 0; j < 4; j++) dst[j] = t4[h][j];
    }
    __syncthreads();    // both groups' cand slots visible

    // ---- per-row final scan: approx top-2 gap test + exact fp32 refine
    if (tid < 64) {
        unsigned long long b1 = U64MAX, b2 = U64MAX;
        const unsigned long long* cr = cand + tid * 32;
#pragma unroll
        for (int j = 0; j < 32; j++) {
            unsigned long long p = cr[j];
            unsigned long long mx = p > b1 ? p : b1;
            b1 = p < b1 ? p : b1;
            b2 = mx < b2 ? mx : b2;
        }
        float v1 = __uint_as_float((uint32_t)(b1 >> 32));
        float v2 = __uint_as_float((uint32_t)(b2 >> 32));
        int best = (int)(uint32_t)(b1 & 0xFFFFFFFFu);
        if (v2 - v1 <= MARGIN) {
            const float* xrow = x + (size_t)(m0 + tid) * D_DIM;
            const float l2q_r = l2q_s[tid];
            float bd = 3.0e38f;
            int   bi = 0x7fffffff;
#pragma unroll 1
            for (int j = 0; j < 32; j++) {
                unsigned long long p = cr[j];
                float pv = __uint_as_float((uint32_t)(p >> 32));
                if (pv <= v1 + MARGIN) {
                    int n = (int)(uint32_t)(p & 0xFFFFFFFFu);
                    float d = exact_dist(xrow, w, n, l2q_r, l2k_s[n]);
                    if (d < bd || (d == bd && n < bi)) { bd = d; bi = n; }
                }
            }
            best = bi;
        }
        best_s[tid] = best;
        atomicAdd(&g_counts[best], 1);
        out[IDX_OFF + m0 + tid] = (float)best;
    }
    __syncthreads();

    // ---- gather z, quantized_st = x + (z - x), loss partial (quarter-row/thread)
    {
        const int r  = tid >> 2;
        const int kb = (tid & 3) << 5;
        const int best = best_s[r];
        const float4* xr = (const float4*)(x + (size_t)(m0 + r) * D_DIM + kb);
        const float4* wz = (const float4*)(w + (size_t)best * D_DIM + kb);
        float4* oq = (float4*)(out + (size_t)(m0 + r) * D_DIM + kb);
        float lsum = 0.f;
#pragma unroll
        for (int i = 0; i < 8; i++) {
            float4 xv = xr[i], z = wz[i];
            float4 qv;
            qv.x = __fadd_rn(xv.x, __fsub_rn(z.x, xv.x));
            qv.y = __fadd_rn(xv.y, __fsub_rn(z.y, xv.y));
            qv.z = __fadd_rn(xv.z, __fsub_rn(z.z, xv.z));
            qv.w = __fadd_rn(xv.w, __fsub_rn(z.w, xv.w));
            oq[i] = qv;
            float d0 = __fsub_rn(qv.x, xv.x), d1 = __fsub_rn(qv.y, xv.y);
            float d2 = __fsub_rn(qv.z, xv.z), d3 = __fsub_rn(qv.w, xv.w);
            lsum += d0 * d0 + d1 * d1 + d2 * d2 + d3 * d3;
        }
#pragma unroll
        for (int o = 16; o > 0; o >>= 1)
            lsum += __shfl_down_sync(0xffffffffu, lsum, o);
        if ((tid & 31) == 0) wsum[wid] = lsum;
    }
    __syncthreads();
    if (tid == 0) {
        float s = 0.f;
#pragma unroll
        for (int i = 0; i < 8; i++) s += wsum[i];
        atomicAdd(&g_loss, s);
    }
}

// ---------------------------------------------------------------------------
// finalize: loss mean + perplexity
// ---------------------------------------------------------------------------
__global__ void finalize_kernel(float* __restrict__ out) {
    int t = threadIdx.x;
    float s = 0.f;
    for (int i = t; i < M_CB; i += 256) {
        float p = (float)g_counts[i] * (1.0f / 65536.0f);
        s += p * logf(p + 1e-10f);
    }
#pragma unroll
    for (int o = 16; o > 0; o >>= 1)
        s += __shfl_down_sync(0xffffffffu, s, o);
    __shared__ float ws[8];
    if ((t & 31) == 0) ws[t >> 5] = s;
    __syncthreads();
    if (t == 0) {
        float tot = 0.f;
#pragma unroll
        for (int i = 0; i < 8; i++) tot += ws[i];
        out[LOSS_OFF] = g_loss * (1.0f / 8388608.0f);
        out[PERP_OFF] = expf(-tot);
    }
}

// ---------------------------------------------------------------------------
extern "C" void kernel_launch(void* const* d_in, const int* in_sizes, int n_in,
                              void* d_out, int out_size) {
    const float* x = (const float*)d_in[0];
    const float* w = (const float*)d_in[1];
    if (n_in >= 2 && in_sizes[0] == M_CB * D_DIM && in_sizes[1] == Q_ELEMS) {
        x = (const float*)d_in[1];
        w = (const float*)d_in[0];
    }
    float* out = (float*)d_out;

    cudaFuncSetAttribute(vq_main_kernel,
                         cudaFuncAttributeMaxDynamicSharedMemorySize, SM_TOTAL);

    prep_kernel<<<128, 256>>>(w);
    vq_main_kernel<<<BN_TOTAL / 64, 256, SM_TOTAL>>>(x, w, out);
    finalize_kernel<<<1, 256>>>(out);
}